// round 1
// baseline (speedup 1.0000x reference)
#include <cuda_runtime.h>
#include <math.h>

#define NN   50000
#define EE   800000
#define DIMM 128
#define ND   (NN*DIMM)
#define ND4  (ND/4)
#define LN_EPS 1e-5f

// ---------------- scratch (device globals; no allocation allowed) ----------------
__device__ float d_xw[ND];       // x @ W_gcn
__device__ float d_xl[ND];       // x @ W_l + b_l
__device__ float d_h[ND];        // GCN pre-LN
__device__ float d_g[ND];        // GAT pre-LN
__device__ float d_fused[ND];
__device__ int   d_cnt[NN];
__device__ int   d_rowptr[NN+1];
__device__ int   d_cursor[NN];
__device__ float d_degw[NN];
__device__ float d_dis[NN];
__device__ int   d_csr_src[EE];
__device__ float d_csr_w[EE];    // dis[src]*edge_weight
__device__ float d_csr_ea[EE];
__device__ float d_stats[8];     // [Sh,SSh,Sg,SSg,Sf,SSf]

__device__ __forceinline__ float gelu_exact(float v) {
    return 0.5f * v * (1.0f + erff(v * 0.7071067811865475f));
}

// ---------------- K0: zero scratch ----------------
__global__ void zero_kernel() {
    if (blockIdx.x == 0 && threadIdx.x < 8) d_stats[threadIdx.x] = 0.f;
    for (int i = blockIdx.x * blockDim.x + threadIdx.x; i < NN; i += gridDim.x * blockDim.x) {
        d_cnt[i] = 0;
        d_degw[i] = 0.f;
    }
}

// ---------------- K1: degree histogram + weighted degree ----------------
__global__ void count_kernel(const int* __restrict__ ei, const float* __restrict__ ew) {
    int e = blockIdx.x * blockDim.x + threadIdx.x;
    if (e >= EE) return;
    int dv = ei[EE + e];
    atomicAdd(&d_cnt[dv], 1);
    atomicAdd(&d_degw[dv], ew[e]);
}

// ---------------- K2: single-block scan -> rowptr/cursor, plus dis[] ----------------
__global__ void scan_kernel() {
    __shared__ int wsum[32];
    __shared__ int carry;
    int t = threadIdx.x, lane = t & 31, wid = t >> 5;
    if (t == 0) { carry = 0; d_rowptr[0] = 0; }
    __syncthreads();
    for (int base = 0; base < NN; base += 1024) {
        int idx = base + t;
        int v = (idx < NN) ? d_cnt[idx] : 0;
        int incl = v;
        #pragma unroll
        for (int o = 1; o < 32; o <<= 1) {
            int u = __shfl_up_sync(0xffffffffu, incl, o);
            if (lane >= o) incl += u;
        }
        if (lane == 31) wsum[wid] = incl;
        __syncthreads();
        if (wid == 0) {
            int wv = wsum[lane];
            #pragma unroll
            for (int o = 1; o < 32; o <<= 1) {
                int u = __shfl_up_sync(0xffffffffu, wv, o);
                if (lane >= o) wv += u;
            }
            wsum[lane] = wv;
        }
        __syncthreads();
        int excl_w = wid ? wsum[wid - 1] : 0;
        int inclusive = carry + excl_w + incl;
        if (idx < NN) {
            d_rowptr[idx + 1] = inclusive;
            d_cursor[idx] = inclusive - v;
            float dw = d_degw[idx];
            d_dis[idx] = (dw > 0.f) ? rsqrtf(fmaxf(dw, 1e-30f)) : 0.f;
        }
        __syncthreads();
        if (t == 1023) carry = inclusive;
        __syncthreads();
    }
}

// ---------------- K3: scatter edges into CSR ----------------
__global__ void scatter_kernel(const int* __restrict__ ei, const float* __restrict__ ew,
                               const float* __restrict__ ea) {
    int e = blockIdx.x * blockDim.x + threadIdx.x;
    if (e >= EE) return;
    int s = ei[e];
    int dv = ei[EE + e];
    int p = atomicAdd(&d_cursor[dv], 1);
    d_csr_src[p] = s;
    d_csr_w[p] = d_dis[s] * ew[e];
    d_csr_ea[p] = ea[e];
}

// ---------------- K4: dual SGEMM  xw = x@W_gcn ; xl = x@W_l + b_l ----------------
// classic 128x128 tile, BK=8, 256 threads, 8x8 per thread. grid.y selects weight.
__global__ void __launch_bounds__(256) gemm_kernel(const float* __restrict__ X,
                                                   const float* __restrict__ W0,
                                                   const float* __restrict__ W1,
                                                   const float* __restrict__ b1) {
    const float* W = blockIdx.y ? W1 : W0;
    float* OUT = blockIdx.y ? d_xl : d_xw;
    __shared__ float xs[8][128];
    __shared__ float ws[8][128];
    int t = threadIdx.x;
    int row0 = blockIdx.x * 128;
    int lrow = t >> 1;
    int lk4 = (t & 1) * 4;
    int wr = t >> 5;
    int wc = (t & 31) * 4;
    int tx = t & 15, ty = t >> 4;
    float acc[8][8];
    #pragma unroll
    for (int i = 0; i < 8; i++)
        #pragma unroll
        for (int j = 0; j < 8; j++) acc[i][j] = 0.f;

    for (int k0 = 0; k0 < 128; k0 += 8) {
        float4 xv = make_float4(0.f, 0.f, 0.f, 0.f);
        int grow = row0 + lrow;
        if (grow < NN) xv = *(const float4*)(X + grow * 128 + k0 + lk4);
        xs[lk4 + 0][lrow] = xv.x;
        xs[lk4 + 1][lrow] = xv.y;
        xs[lk4 + 2][lrow] = xv.z;
        xs[lk4 + 3][lrow] = xv.w;
        *(float4*)&ws[wr][wc] = *(const float4*)(W + (k0 + wr) * 128 + wc);
        __syncthreads();
        #pragma unroll
        for (int kk = 0; kk < 8; kk++) {
            float a[8], b[8];
            *(float4*)(a)     = *(float4*)&xs[kk][ty * 8];
            *(float4*)(a + 4) = *(float4*)&xs[kk][ty * 8 + 4];
            *(float4*)(b)     = *(float4*)&ws[kk][tx * 8];
            *(float4*)(b + 4) = *(float4*)&ws[kk][tx * 8 + 4];
            #pragma unroll
            for (int i = 0; i < 8; i++)
                #pragma unroll
                for (int j = 0; j < 8; j++) acc[i][j] += a[i] * b[j];
        }
        __syncthreads();
    }
    float bias[8];
    if (blockIdx.y) {
        *(float4*)(bias)     = *(const float4*)(b1 + tx * 8);
        *(float4*)(bias + 4) = *(const float4*)(b1 + tx * 8 + 4);
    } else {
        #pragma unroll
        for (int j = 0; j < 8; j++) bias[j] = 0.f;
    }
    #pragma unroll
    for (int i = 0; i < 8; i++) {
        int grow = row0 + ty * 8 + i;
        if (grow < NN) {
            float o[8];
            #pragma unroll
            for (int j = 0; j < 8; j++) o[j] = acc[i][j] + bias[j];
            *(float4*)(OUT + grow * 128 + tx * 8)     = *(float4*)(o);
            *(float4*)(OUT + grow * 128 + tx * 8 + 4) = *(float4*)(o + 4);
        }
    }
}

// ---------------- K5: warp-per-dst aggregation (GCN sum + GAT online softmax) ----------------
__global__ void __launch_bounds__(256) agg_kernel(const float* __restrict__ b_gcn,
                                                  const float* __restrict__ b_gat,
                                                  const float* __restrict__ W_edge,
                                                  const float* __restrict__ att) {
    int gw = (blockIdx.x * blockDim.x + threadIdx.x) >> 5;
    int lane = threadIdx.x & 31;
    if (gw >= NN) return;

    int r0 = d_rowptr[gw];
    int r1 = d_rowptr[gw + 1];
    float disd = d_dis[gw];

    const float4* xl4 = (const float4*)d_xl;
    const float4* xw4 = (const float4*)d_xw;
    float4 xld = xl4[gw * 32 + lane];
    float4 we  = __ldg(((const float4*)W_edge) + lane);
    float4 at  = __ldg(((const float4*)att) + lane);

    float4 hacc = make_float4(0.f, 0.f, 0.f, 0.f);
    float4 acc  = make_float4(0.f, 0.f, 0.f, 0.f);
    float m = -INFINITY, dsum = 0.f;

    for (int p = r0; p < r1; ++p) {
        int src   = __ldg(&d_csr_src[p]);
        float cw  = __ldg(&d_csr_w[p]) * disd;
        float eav = __ldg(&d_csr_ea[p]);
        float4 xls = xl4[src * 32 + lane];
        float4 xws = xw4[src * 32 + lane];

        hacc.x += cw * xws.x; hacc.y += cw * xws.y;
        hacc.z += cw * xws.z; hacc.w += cw * xws.w;

        float4 z;
        z.x = xld.x + xls.x + eav * we.x;
        z.y = xld.y + xls.y + eav * we.y;
        z.z = xld.z + xls.z + eav * we.z;
        z.w = xld.w + xls.w + eav * we.w;
        z.x = z.x > 0.f ? z.x : 0.2f * z.x;
        z.y = z.y > 0.f ? z.y : 0.2f * z.y;
        z.z = z.z > 0.f ? z.z : 0.2f * z.z;
        z.w = z.w > 0.f ? z.w : 0.2f * z.w;
        float part = z.x * at.x + z.y * at.y + z.z * at.z + z.w * at.w;
        part += __shfl_xor_sync(0xffffffffu, part, 1);
        part += __shfl_xor_sync(0xffffffffu, part, 2);
        part += __shfl_xor_sync(0xffffffffu, part, 4);   // per-head logit (8-lane groups)

        float mn = fmaxf(m, part);
        float sc = __expf(m - mn);     // 0 on first edge (m = -inf)
        float pe = __expf(part - mn);
        dsum = dsum * sc + pe;
        acc.x = acc.x * sc + pe * xls.x;
        acc.y = acc.y * sc + pe * xls.y;
        acc.z = acc.z * sc + pe * xls.z;
        acc.w = acc.w * sc + pe * xls.w;
        m = mn;
    }

    float inv = 1.0f / (dsum + 1e-16f);
    float4 bc = __ldg(((const float4*)b_gcn) + lane);
    float4 bg = __ldg(((const float4*)b_gat) + lane);
    float4 ho = make_float4(hacc.x + bc.x, hacc.y + bc.y, hacc.z + bc.z, hacc.w + bc.w);
    float4 go = make_float4(acc.x * inv + bg.x, acc.y * inv + bg.y,
                            acc.z * inv + bg.z, acc.w * inv + bg.w);
    ((float4*)d_h)[gw * 32 + lane] = ho;
    ((float4*)d_g)[gw * 32 + lane] = go;
}

// ---------------- K6: sum/sumsq of h and g ----------------
__global__ void stats_hg_kernel() {
    float sh = 0.f, ssh = 0.f, sg = 0.f, ssg = 0.f;
    const float4* h4 = (const float4*)d_h;
    const float4* g4 = (const float4*)d_g;
    for (int i = blockIdx.x * blockDim.x + threadIdx.x; i < ND4; i += gridDim.x * blockDim.x) {
        float4 a = h4[i];
        sh  += a.x + a.y + a.z + a.w;
        ssh += a.x * a.x + a.y * a.y + a.z * a.z + a.w * a.w;
        float4 b = g4[i];
        sg  += b.x + b.y + b.z + b.w;
        ssg += b.x * b.x + b.y * b.y + b.z * b.z + b.w * b.w;
    }
    #pragma unroll
    for (int o = 16; o; o >>= 1) {
        sh  += __shfl_down_sync(0xffffffffu, sh, o);
        ssh += __shfl_down_sync(0xffffffffu, ssh, o);
        sg  += __shfl_down_sync(0xffffffffu, sg, o);
        ssg += __shfl_down_sync(0xffffffffu, ssg, o);
    }
    __shared__ float sm[4][8];
    int wid = threadIdx.x >> 5, lane = threadIdx.x & 31;
    if (lane == 0) { sm[0][wid] = sh; sm[1][wid] = ssh; sm[2][wid] = sg; sm[3][wid] = ssg; }
    __syncthreads();
    if (threadIdx.x == 0) {
        float a = 0.f, b = 0.f, c = 0.f, d = 0.f;
        for (int i = 0; i < 8; i++) { a += sm[0][i]; b += sm[1][i]; c += sm[2][i]; d += sm[3][i]; }
        atomicAdd(&d_stats[0], a);
        atomicAdd(&d_stats[1], b);
        atomicAdd(&d_stats[2], c);
        atomicAdd(&d_stats[3], d);
    }
}

// ---------------- K7: LN+gelu both branches, residual, fuse; stats of fused ----------------
__global__ void fuse_kernel(const float* __restrict__ x,
                            const float* __restrict__ gcn_nw, const float* __restrict__ gcn_nb,
                            const float* __restrict__ gat_nw, const float* __restrict__ gat_nb,
                            const float* __restrict__ alpha) {
    const float M = (float)ND;
    float mu_h = d_stats[0] / M;
    float inv_h = 1.0f / (sqrtf(fmaxf(d_stats[1] / M - mu_h * mu_h, 0.f)) + LN_EPS);
    float mu_g = d_stats[2] / M;
    float inv_g = 1.0f / (sqrtf(fmaxf(d_stats[3] / M - mu_g * mu_g, 0.f)) + LN_EPS);
    float a0 = alpha[0], a1 = alpha[1];
    float mx = fmaxf(a0, a1);
    float e0 = expf(a0 - mx), e1 = expf(a1 - mx);
    float w0 = e0 / (e0 + e1), w1 = e1 / (e0 + e1);

    float sf = 0.f, ssf = 0.f;
    const float4* x4 = (const float4*)x;
    const float4* h4 = (const float4*)d_h;
    const float4* g4 = (const float4*)d_g;
    float4* f4 = (float4*)d_fused;
    for (int i = blockIdx.x * blockDim.x + threadIdx.x; i < ND4; i += gridDim.x * blockDim.x) {
        int c4 = i & 31;
        float4 nwh = __ldg(((const float4*)gcn_nw) + c4);
        float4 nbh = __ldg(((const float4*)gcn_nb) + c4);
        float4 nwg = __ldg(((const float4*)gat_nw) + c4);
        float4 nbg = __ldg(((const float4*)gat_nb) + c4);
        float4 hv = h4[i], gv = g4[i], xv = x4[i];
        float4 fv;
        {
            float t = gelu_exact((hv.x - mu_h) * inv_h * nwh.x + nbh.x);
            float u = gelu_exact((gv.x - mu_g) * inv_g * nwg.x + nbg.x);
            fv.x = w0 * (xv.x + t) + w1 * (xv.x + u);
            t = gelu_exact((hv.y - mu_h) * inv_h * nwh.y + nbh.y);
            u = gelu_exact((gv.y - mu_g) * inv_g * nwg.y + nbg.y);
            fv.y = w0 * (xv.y + t) + w1 * (xv.y + u);
            t = gelu_exact((hv.z - mu_h) * inv_h * nwh.z + nbh.z);
            u = gelu_exact((gv.z - mu_g) * inv_g * nwg.z + nbg.z);
            fv.z = w0 * (xv.z + t) + w1 * (xv.z + u);
            t = gelu_exact((hv.w - mu_h) * inv_h * nwh.w + nbh.w);
            u = gelu_exact((gv.w - mu_g) * inv_g * nwg.w + nbg.w);
            fv.w = w0 * (xv.w + t) + w1 * (xv.w + u);
        }
        f4[i] = fv;
        sf  += fv.x + fv.y + fv.z + fv.w;
        ssf += fv.x * fv.x + fv.y * fv.y + fv.z * fv.z + fv.w * fv.w;
    }
    #pragma unroll
    for (int o = 16; o; o >>= 1) {
        sf  += __shfl_down_sync(0xffffffffu, sf, o);
        ssf += __shfl_down_sync(0xffffffffu, ssf, o);
    }
    __shared__ float sm[2][8];
    int wid = threadIdx.x >> 5, lane = threadIdx.x & 31;
    if (lane == 0) { sm[0][wid] = sf; sm[1][wid] = ssf; }
    __syncthreads();
    if (threadIdx.x == 0) {
        float a = 0.f, b = 0.f;
        for (int i = 0; i < 8; i++) { a += sm[0][i]; b += sm[1][i]; }
        atomicAdd(&d_stats[4], a);
        atomicAdd(&d_stats[5], b);
    }
}

// ---------------- K8: final LN + gelu -> out ----------------
__global__ void out_kernel(const float* __restrict__ onw, const float* __restrict__ onb,
                           float* __restrict__ out) {
    const float M = (float)ND;
    float mu = d_stats[4] / M;
    float inv = 1.0f / (sqrtf(fmaxf(d_stats[5] / M - mu * mu, 0.f)) + LN_EPS);
    const float4* f4 = (const float4*)d_fused;
    float4* o4 = (float4*)out;
    for (int i = blockIdx.x * blockDim.x + threadIdx.x; i < ND4; i += gridDim.x * blockDim.x) {
        int c4 = i & 31;
        float4 nw = __ldg(((const float4*)onw) + c4);
        float4 nb = __ldg(((const float4*)onb) + c4);
        float4 fv = f4[i];
        float4 ov;
        ov.x = gelu_exact((fv.x - mu) * inv * nw.x + nb.x);
        ov.y = gelu_exact((fv.y - mu) * inv * nw.y + nb.y);
        ov.z = gelu_exact((fv.z - mu) * inv * nw.z + nb.z);
        ov.w = gelu_exact((fv.w - mu) * inv * nw.w + nb.w);
        o4[i] = ov;
    }
}

// ---------------- launch ----------------
extern "C" void kernel_launch(void* const* d_in, const int* in_sizes, int n_in,
                              void* d_out, int out_size) {
    const float* x      = (const float*)d_in[0];
    const int*   ei     = (const int*)d_in[1];
    const float* ew     = (const float*)d_in[2];
    const float* ea     = (const float*)d_in[3];
    const float* W_gcn  = (const float*)d_in[4];
    const float* b_gcn  = (const float*)d_in[5];
    const float* W_l    = (const float*)d_in[6];
    const float* b_l    = (const float*)d_in[7];
    const float* W_edge = (const float*)d_in[8];
    const float* att    = (const float*)d_in[9];
    const float* b_gat  = (const float*)d_in[10];
    const float* gcn_nw = (const float*)d_in[11];
    const float* gcn_nb = (const float*)d_in[12];
    const float* gat_nw = (const float*)d_in[13];
    const float* gat_nb = (const float*)d_in[14];
    const float* out_nw = (const float*)d_in[15];
    const float* out_nb = (const float*)d_in[16];
    const float* alpha  = (const float*)d_in[17];
    float* out = (float*)d_out;

    zero_kernel<<<256, 256>>>();
    count_kernel<<<(EE + 255) / 256, 256>>>(ei, ew);
    scan_kernel<<<1, 1024>>>();
    scatter_kernel<<<(EE + 255) / 256, 256>>>(ei, ew, ea);
    dim3 gg((NN + 127) / 128, 2);
    gemm_kernel<<<gg, 256>>>(x, W_gcn, W_l, b_l);
    agg_kernel<<<(NN + 7) / 8, 256>>>(b_gcn, b_gat, W_edge, att);
    stats_hg_kernel<<<1480, 256>>>(); 
    fuse_kernel<<<1480, 256>>>(x, gcn_nw, gcn_nb, gat_nw, gat_nb, alpha);
    out_kernel<<<1480, 256>>>(out_nw, out_nb, out);
}